// round 10
// baseline (speedup 1.0000x reference)
#include <cuda_runtime.h>
#include <cuda_bf16.h>
#include <cstdint>

// LSTM B=2048,T=512,F=64,H=128.
// Pass 1 (parallel): xz = x@Wx via 3-term split bf16 MMA, raw accumulator
//   fragments stored to g_xz in (cta,t,tid,reg) order.
// Pass 2 (recurrent): z = xz + h@Wh via same MMA structure, K=128, 2-CTA
//   cluster (rank owns 256 gate cols), double-buffered A tile, one cluster
//   sync per step. Gate order i,f,g,o handled by gate-interleaved n cols.

#define T_DIM 512
#define F_DIM 64
#define H_DIM 128
#define TFX   (T_DIM * F_DIM)
#define THX   (T_DIM * H_DIM)
#define NTH   256
#define PT    32                 // timesteps per pre-pass block

// recurrent smem layout
#define OFF_WHI 0
#define OFF_WLO 65536
#define OFF_A   131072           // 2 buffers x (8192 hi + 8192 lo)
#define OFF_SHI 163840
#define OFF_SLO 167936
#define SMEM_REC 172032

// pre-pass smem layout
#define P_WHI 0
#define P_WLO 32768
#define P_AHI 65536
#define P_ALO 69632
#define SMEM_PRE 73728

typedef uint32_t u32;
typedef unsigned long long u64;

__device__ float g_xz[536870912];   // 128 ctas x 512 t x 256 thr x 32 regs (2.1 GB)

static __device__ __forceinline__ u32 smaddr(const void* p) {
    u32 a;
    asm("{ .reg .u64 t; cvta.to.shared.u64 t, %1; cvt.u32.u64 %0, t; }" : "=r"(a) : "l"(p));
    return a;
}
static __device__ __forceinline__ u32 ctarank() {
    u32 r; asm("mov.u32 %0, %%cluster_ctarank;" : "=r"(r)); return r;
}
static __device__ __forceinline__ u32 mapa_(u32 a, u32 r) {
    u32 d; asm("mapa.shared::cluster.u32 %0, %1, %2;" : "=r"(d) : "r"(a), "r"(r)); return d;
}
static __device__ __forceinline__ void csync() {
    asm volatile("barrier.cluster.arrive.aligned;" ::: "memory");
    asm volatile("barrier.cluster.wait.aligned;" ::: "memory");
}
static __device__ __forceinline__ void ldm4(u32& a, u32& b, u32& c, u32& d, u32 ad) {
    asm volatile("ldmatrix.sync.aligned.m8n8.x4.shared.b16 {%0,%1,%2,%3}, [%4];"
                 : "=r"(a), "=r"(b), "=r"(c), "=r"(d) : "r"(ad));
}
static __device__ __forceinline__ void ldm2(u32& a, u32& b, u32 ad) {
    asm volatile("ldmatrix.sync.aligned.m8n8.x2.shared.b16 {%0,%1}, [%2];"
                 : "=r"(a), "=r"(b) : "r"(ad));
}
static __device__ __forceinline__ void mma_bf16(float& c0, float& c1, float& c2, float& c3,
                                                u32 a0, u32 a1, u32 a2, u32 a3, u32 b0, u32 b1) {
    asm volatile(
        "mma.sync.aligned.m16n8k16.row.col.f32.bf16.bf16.f32 "
        "{%0,%1,%2,%3}, {%4,%5,%6,%7}, {%8,%9}, {%0,%1,%2,%3};"
        : "+f"(c0), "+f"(c1), "+f"(c2), "+f"(c3)
        : "r"(a0), "r"(a1), "r"(a2), "r"(a3), "r"(b0), "r"(b1));
}
static __device__ __forceinline__ void st_rem64(u32 ad, u64 v) {
    asm volatile("st.shared::cluster.b64 [%0], %1;" :: "r"(ad), "l"(v) : "memory");
}
static __device__ __forceinline__ float sigf(float v) {
    return __fdividef(1.0f, 1.0f + __expf(-v));
}
static __device__ __forceinline__ float tanhf_(float v) {
    return __fdividef(2.0f, 1.0f + __expf(-2.0f * v)) - 1.0f;
}
static __device__ __forceinline__ u32 cat2(__nv_bfloat16 a, __nv_bfloat16 b) {
    return (u32)__bfloat16_as_ushort(a) | ((u32)__bfloat16_as_ushort(b) << 16);
}
static __device__ __forceinline__ void split8(const float* v, uint4& h, uint4& l) {
    __nv_bfloat16 bh[8];
    float rr[8];
#pragma unroll
    for (int i = 0; i < 8; i++) {
        bh[i] = __float2bfloat16(v[i]);
        rr[i] = v[i] - __bfloat162float(bh[i]);
    }
    h.x = cat2(bh[0], bh[1]); h.y = cat2(bh[2], bh[3]);
    h.z = cat2(bh[4], bh[5]); h.w = cat2(bh[6], bh[7]);
    l.x = cat2(__float2bfloat16(rr[0]), __float2bfloat16(rr[1]));
    l.y = cat2(__float2bfloat16(rr[2]), __float2bfloat16(rr[3]));
    l.z = cat2(__float2bfloat16(rr[4]), __float2bfloat16(rr[5]));
    l.w = cat2(__float2bfloat16(rr[6]), __float2bfloat16(rr[7]));
}

// ============================ pre-pass =====================================
__global__ __launch_bounds__(NTH, 1)
void lstm_prepass(const float* __restrict__ x, const float* __restrict__ Wx)
{
    extern __shared__ char smc[];
    const u32 sb = smaddr(smc);
    const int tid = threadIdx.x, w = tid >> 5, lane = tid & 31;
    const int pr = blockIdx.x & 127;        // virtual recurrent-CTA id
    const int t0 = (blockIdx.x >> 7) * PT;
    const int rank = pr & 1;
    const long b0 = (long)(pr >> 1) * 32;

    // Wx hi/lo into ldmatrix layout [n 0..255][k 0..63], 128B rows
    for (int idx = tid; idx < 64 * 256; idx += NTH) {
        int k = idx >> 8, nn = idx & 255;
        int col = (nn & 3) * 128 + 64 * rank + (nn >> 2);
        float wv = Wx[k * 512 + col];
        __nv_bfloat16 bh = __float2bfloat16(wv);
        __nv_bfloat16 bl = __float2bfloat16(wv - __bfloat162float(bh));
        u32 off = (u32)(nn * 128 + (((k >> 3) ^ (nn & 7)) << 4) + (k & 7) * 2);
        *(__nv_bfloat16*)(smc + P_WHI + off) = bh;
        *(__nv_bfloat16*)(smc + P_WLO + off) = bl;
    }
    __syncthreads();

    // fragment addressing (identical decode to recurrent kernel)
    const int amat = lane >> 3, aidx = lane & 7;
    const int arow = ((amat & 1) << 3) + aidx;
    const int aksel = amat >> 1;
    const int a7 = arow & 7;
    const u32 aob0 = sb + P_AHI + (u32)(arow * 128);
    const u32 aob1 = sb + P_AHI + (u32)((arow + 16) * 128);
    const int bl_ = lane & 15, brin = bl_ & 7, bksel = bl_ >> 3;
    u32 bob[4];
#pragma unroll
    for (int nj = 0; nj < 4; nj++)
        bob[nj] = sb + P_WHI + (u32)((32 * w + 8 * nj + brin) * 128);

    // A build mapping
    const int prow = tid >> 3, pj = tid & 7;
    const float* xbase = x + (b0 + prow) * (long)TFX + 8 * pj;
    const u32 offx = (u32)(prow * 128 + ((pj ^ (prow & 7)) << 4));

    float xv[8];
    {
        float4 q0 = *(const float4*)(xbase + t0 * F_DIM);
        float4 q1 = *(const float4*)(xbase + t0 * F_DIM + 4);
        xv[0]=q0.x; xv[1]=q0.y; xv[2]=q0.z; xv[3]=q0.w;
        xv[4]=q1.x; xv[5]=q1.y; xv[6]=q1.z; xv[7]=q1.w;
    }

    for (int tt = 0; tt < PT; tt++) {
        const int t = t0 + tt;
        uint4 xh, xl;
        split8(xv, xh, xl);
        *(uint4*)(smc + P_AHI + offx) = xh;
        *(uint4*)(smc + P_ALO + offx) = xl;
        __syncthreads();

        if (tt + 1 < PT) {
            float4 q0 = *(const float4*)(xbase + (t + 1) * F_DIM);
            float4 q1 = *(const float4*)(xbase + (t + 1) * F_DIM + 4);
            xv[0]=q0.x; xv[1]=q0.y; xv[2]=q0.z; xv[3]=q0.w;
            xv[4]=q1.x; xv[5]=q1.y; xv[6]=q1.z; xv[7]=q1.w;
        }

        float acc[2][4][4];
#pragma unroll
        for (int mi = 0; mi < 2; mi++)
#pragma unroll
            for (int nj = 0; nj < 4; nj++)
#pragma unroll
                for (int e = 0; e < 4; e++) acc[mi][nj][e] = 0.0f;

#pragma unroll
        for (int ks = 0; ks < 4; ks++) {
            const u32 swA = 16u * (u32)((2 * ks + aksel) ^ a7);
            u32 Ah0[4], Ah1[4], Al0[4], Al1[4];
            ldm4(Ah0[0], Ah0[1], Ah0[2], Ah0[3], aob0 + swA);
            ldm4(Ah1[0], Ah1[1], Ah1[2], Ah1[3], aob1 + swA);
            ldm4(Al0[0], Al0[1], Al0[2], Al0[3], aob0 + swA + 4096);
            ldm4(Al1[0], Al1[1], Al1[2], Al1[3], aob1 + swA + 4096);
            const u32 swB = 16u * (u32)((2 * ks + bksel) ^ brin);
#pragma unroll
            for (int nj = 0; nj < 4; nj++) {
                u32 bh0, bh1, bl0, bl1;
                ldm2(bh0, bh1, bob[nj] + swB);
                ldm2(bl0, bl1, bob[nj] + swB + 32768);
                mma_bf16(acc[0][nj][0], acc[0][nj][1], acc[0][nj][2], acc[0][nj][3],
                         Ah0[0], Ah0[1], Ah0[2], Ah0[3], bh0, bh1);
                mma_bf16(acc[1][nj][0], acc[1][nj][1], acc[1][nj][2], acc[1][nj][3],
                         Ah1[0], Ah1[1], Ah1[2], Ah1[3], bh0, bh1);
                mma_bf16(acc[0][nj][0], acc[0][nj][1], acc[0][nj][2], acc[0][nj][3],
                         Ah0[0], Ah0[1], Ah0[2], Ah0[3], bl0, bl1);
                mma_bf16(acc[1][nj][0], acc[1][nj][1], acc[1][nj][2], acc[1][nj][3],
                         Ah1[0], Ah1[1], Ah1[2], Ah1[3], bl0, bl1);
                mma_bf16(acc[0][nj][0], acc[0][nj][1], acc[0][nj][2], acc[0][nj][3],
                         Al0[0], Al0[1], Al0[2], Al0[3], bh0, bh1);
                mma_bf16(acc[1][nj][0], acc[1][nj][1], acc[1][nj][2], acc[1][nj][3],
                         Al1[0], Al1[1], Al1[2], Al1[3], bh0, bh1);
            }
        }

        // store raw fragments (cta, t, tid, reg)
        float* dst = g_xz + ((long)pr * T_DIM + t) * 8192 + tid * 32;
        const float* a0 = &acc[0][0][0];
#pragma unroll
        for (int i2 = 0; i2 < 8; i2++)
            *(float4*)(dst + 4 * i2) = *(const float4*)(a0 + 4 * i2);
        __syncthreads();
    }
}

// ============================ recurrent ====================================
__global__ void __cluster_dims__(2, 1, 1) __launch_bounds__(NTH, 1)
lstm_rec(const float* __restrict__ Wh, const float* __restrict__ bias,
         float* __restrict__ out)
{
    extern __shared__ char smc[];
    const u32 sb = smaddr(smc);
    const int tid = threadIdx.x, w = tid >> 5, lane = tid & 31;
    const u32 rank = ctarank();
    const long b0 = (long)(blockIdx.x >> 1) * 32;

    // Wh hi/lo into ldmatrix layout [n 0..255][k 0..127], 256B rows
    for (int idx = tid; idx < 128 * 256; idx += NTH) {
        int k = idx >> 8, nn = idx & 255;
        int col = (nn & 3) * 128 + 64 * (int)rank + (nn >> 2);
        float wv = Wh[k * 512 + col];
        __nv_bfloat16 bh = __float2bfloat16(wv);
        __nv_bfloat16 bl = __float2bfloat16(wv - __bfloat162float(bh));
        u32 off = (u32)(nn * 256 + (((k >> 3) ^ (nn & 7)) << 4) + (k & 7) * 2);
        *(__nv_bfloat16*)(smc + OFF_WHI + off) = bh;
        *(__nv_bfloat16*)(smc + OFF_WLO + off) = bl;
    }
    // zero both A buffers (h0 = 0)
    for (int i = tid; i < 32768 / 8; i += NTH)
        ((u64*)(smc + OFF_A))[i] = 0ull;
    __syncthreads();

    // fragment addressing
    const int amat = lane >> 3, aidx = lane & 7;
    const int arow = ((amat & 1) << 3) + aidx;
    const int aksel = amat >> 1;
    const int a7 = arow & 7;
    const int bl_ = lane & 15, brin = bl_ & 7, bksel = bl_ >> 3;
    u32 bob[4];
#pragma unroll
    for (int nj = 0; nj < 4; nj++)
        bob[nj] = sb + OFF_WHI + (u32)((32 * w + 8 * nj + brin) * 256);

    // epilogue mapping + bias + c state
    const int q = lane >> 2, t4 = lane & 3, rs = t4 & 1, jb2 = t4 >> 1;
    float bi[4], bff[4], bg[4], bo[4];
#pragma unroll
    for (int nj = 0; nj < 4; nj++) {
        int jl = 8 * w + 2 * nj + jb2;
        int cb = 64 * (int)rank + jl;
        bi[nj]  = bias[cb];
        bff[nj] = bias[128 + cb];
        bg[nj]  = bias[256 + cb];
        bo[nj]  = bias[384 + cb];
    }
    float cst[2][4];
#pragma unroll
    for (int mi = 0; mi < 2; mi++)
#pragma unroll
        for (int nj = 0; nj < 4; nj++) cst[mi][nj] = 0.0f;

    // pass-2 (h writer) mapping: all 256 threads; k chunk = 64*rank + 8*pj
    const int prow = tid >> 3, pj = tid & 7;
    const int kk = 8 * (int)rank + pj;           // 16B-unit index in k
    const u32 offh = (u32)(prow * 256 + ((kk ^ (prow & 7)) << 4));
    const u32 peerA = mapa_(sb + OFF_A, rank ^ 1);

    const float* xzp = g_xz + (long)blockIdx.x * T_DIM * 8192 + tid * 32;

    for (int t = 0; t < T_DIM; t++) {
        csync();    // A(t) buffer complete cluster-wide

        // xz(t): issue early, consumed in epilogue (hides under MMA)
        float xz[32];
        {
            const float* s = xzp + (long)t * 8192;
#pragma unroll
            for (int i2 = 0; i2 < 8; i2++)
                *(float4*)(xz + 4 * i2) = *(const float4*)(s + 4 * i2);
        }

        const u32 abase = sb + OFF_A + (u32)((t & 1) * 16384);
        const u32 aob0 = abase + (u32)(arow * 256);
        const u32 aob1 = abase + (u32)((arow + 16) * 256);

        float acc[2][4][4];
#pragma unroll
        for (int mi = 0; mi < 2; mi++)
#pragma unroll
            for (int nj = 0; nj < 4; nj++)
#pragma unroll
                for (int e = 0; e < 4; e++) acc[mi][nj][e] = 0.0f;

#pragma unroll
        for (int ks = 0; ks < 8; ks++) {
            const u32 swA = 16u * (u32)((2 * ks + aksel) ^ a7);
            u32 Ah0[4], Ah1[4], Al0[4], Al1[4];
            ldm4(Ah0[0], Ah0[1], Ah0[2], Ah0[3], aob0 + swA);
            ldm4(Ah1[0], Ah1[1], Ah1[2], Ah1[3], aob1 + swA);
            ldm4(Al0[0], Al0[1], Al0[2], Al0[3], aob0 + swA + 8192);
            ldm4(Al1[0], Al1[1], Al1[2], Al1[3], aob1 + swA + 8192);
            const u32 swB = 16u * (u32)((2 * ks + bksel) ^ brin);
#pragma unroll
            for (int nj = 0; nj < 4; nj++) {
                u32 bh0, bh1, bl0, bl1;
                ldm2(bh0, bh1, bob[nj] + swB);
                ldm2(bl0, bl1, bob[nj] + swB + 65536);
                mma_bf16(acc[0][nj][0], acc[0][nj][1], acc[0][nj][2], acc[0][nj][3],
                         Ah0[0], Ah0[1], Ah0[2], Ah0[3], bh0, bh1);
                mma_bf16(acc[1][nj][0], acc[1][nj][1], acc[1][nj][2], acc[1][nj][3],
                         Ah1[0], Ah1[1], Ah1[2], Ah1[3], bh0, bh1);
                mma_bf16(acc[0][nj][0], acc[0][nj][1], acc[0][nj][2], acc[0][nj][3],
                         Ah0[0], Ah0[1], Ah0[2], Ah0[3], bl0, bl1);
                mma_bf16(acc[1][nj][0], acc[1][nj][1], acc[1][nj][2], acc[1][nj][3],
                         Ah1[0], Ah1[1], Ah1[2], Ah1[3], bl0, bl1);
                mma_bf16(acc[0][nj][0], acc[0][nj][1], acc[0][nj][2], acc[0][nj][3],
                         Al0[0], Al0[1], Al0[2], Al0[3], bh0, bh1);
                mma_bf16(acc[1][nj][0], acc[1][nj][1], acc[1][nj][2], acc[1][nj][3],
                         Al1[0], Al1[1], Al1[2], Al1[3], bh0, bh1);
            }
        }

        // epilogue: add xz fragments, shfl-exchange gates, state update
#pragma unroll
        for (int mi = 0; mi < 2; mi++) {
#pragma unroll
            for (int nj = 0; nj < 4; nj++) {
                const float* xq = xz + (mi * 4 + nj) * 4;
                float v0 = acc[mi][nj][0] + xq[0];
                float v1 = acc[mi][nj][1] + xq[1];
                float v2 = acc[mi][nj][2] + xq[2];
                float v3 = acc[mi][nj][3] + xq[3];
                float p0 = __shfl_xor_sync(0xffffffffu, v0, 1);
                float p1 = __shfl_xor_sync(0xffffffffu, v1, 1);
                float p2 = __shfl_xor_sync(0xffffffffu, v2, 1);
                float p3 = __shfl_xor_sync(0xffffffffu, v3, 1);
                float zi = rs ? p2 : v0;
                float zf = rs ? p3 : v1;
                float zg = rs ? v2 : p0;
                float zo = rs ? v3 : p1;
                float ig = sigf(zi + bi[nj]);
                float fg = sigf(zf + bff[nj]);
                float gg = tanhf_(zg + bg[nj]);
                float og = sigf(zo + bo[nj]);
                float cn = fmaf(fg, cst[mi][nj], ig * gg);
                cst[mi][nj] = cn;
                float h = og * tanhf_(cn);
                int jl = 8 * w + 2 * nj + jb2;
                int row = q + 8 * rs + 16 * mi;
                out[(b0 + row) * (long)THX + (long)t * H_DIM + 64 * (int)rank + jl] = h;
                __nv_bfloat16 hb = __float2bfloat16(h);
                __nv_bfloat16 hr = __float2bfloat16(h - __bfloat162float(hb));
                *(__nv_bfloat16*)(smc + OFF_SHI + (row * 64 + jl) * 2) = hb;
                *(__nv_bfloat16*)(smc + OFF_SLO + (row * 64 + jl) * 2) = hr;
            }
        }

        __syncthreads();   // stage complete (CTA-local; A(t+1) is the other buffer)

        if (t + 1 < T_DIM) {
            const u32 nb = (u32)(((t + 1) & 1) * 16384);
            uint4 hh = *(uint4*)(smc + OFF_SHI + prow * 128 + pj * 16);
            uint4 hl = *(uint4*)(smc + OFF_SLO + prow * 128 + pj * 16);
            *(uint4*)(smc + OFF_A + nb + offh) = hh;
            *(uint4*)(smc + OFF_A + nb + 8192 + offh) = hl;
            const u32 pa = peerA + nb + offh;
            st_rem64(pa,            (u64)hh.x | ((u64)hh.y << 32));
            st_rem64(pa + 8,        (u64)hh.z | ((u64)hh.w << 32));
            st_rem64(pa + 8192,     (u64)hl.x | ((u64)hl.y << 32));
            st_rem64(pa + 8192 + 8, (u64)hl.z | ((u64)hl.w << 32));
        }
    }
    csync();    // drain in-flight remote stores before exit
}

extern "C" void kernel_launch(void* const* d_in, const int* in_sizes, int n_in,
                              void* d_out, int out_size) {
    const float* x  = (const float*)d_in[0];   // [B,T,F]
    const float* Wx = (const float*)d_in[1];   // [F,512]
    const float* Wh = (const float*)d_in[2];   // [H,512]
    const float* b  = (const float*)d_in[3];   // [512]
    float* out = (float*)d_out;                // [B,T,H]

    cudaFuncSetAttribute(lstm_prepass, cudaFuncAttributeMaxDynamicSharedMemorySize, SMEM_PRE);
    cudaFuncSetAttribute(lstm_rec, cudaFuncAttributeMaxDynamicSharedMemorySize, SMEM_REC);

    lstm_prepass<<<128 * (T_DIM / PT), NTH, SMEM_PRE>>>(x, Wx);
    lstm_rec<<<128, NTH, SMEM_REC>>>(Wh, b, out);
}

// round 11
// speedup vs baseline: 2.3879x; 2.3879x over previous
#include <cuda_runtime.h>
#include <cuda_fp16.h>
#include <cuda_bf16.h>
#include <cstdint>

// LSTM B=2048,T=512,F=64,H=128.
// Prepass: xz = x@Wx + b (bf16 3-term split, ~fp32 exact), stored as raw MMA
//   accumulator quads in g_xz[cta][t][nj][tid][4] matching the rec fragment map.
// Rec: z = xz + h@Wh with SINGLE-TERM fp16 mma.sync. M=16 rows/CTA, N=512,
//   K=128, 128 independent CTAs, no cluster. W fp16 in smem (131KB); B-frags
//   for nj<4 hoisted to registers for the whole time loop.

#define T_DIM 512
#define F_DIM 64
#define H_DIM 128
#define TFX   (T_DIM * F_DIM)
#define THX   (T_DIM * H_DIM)
#define NTH   256
#define PT    64

// rec smem
#define R_W   0
#define R_A   131072            // 2 x 4096 (A fp16 [16][128], double buffer)
#define R_ST  139264            // stage fp32 [16][132]
#define SMEM_REC (139264 + 16*132*4)

// prepass smem
#define P_WHI 0
#define P_WLO 65536
#define P_AHI 131072
#define P_ALO 135168
#define SMEM_PRE 139264

typedef uint32_t u32;
typedef unsigned long long u64;

__device__ float g_xz[536870912];   // 128 x 512 x 8 x 256 x 4 floats (2.1 GB)

static __device__ __forceinline__ u32 smaddr(const void* p) {
    u32 a;
    asm("{ .reg .u64 t; cvta.to.shared.u64 t, %1; cvt.u32.u64 %0, t; }" : "=r"(a) : "l"(p));
    return a;
}
static __device__ __forceinline__ void ldm4(u32* r, u32 ad) {
    asm volatile("ldmatrix.sync.aligned.m8n8.x4.shared.b16 {%0,%1,%2,%3}, [%4];"
                 : "=r"(r[0]), "=r"(r[1]), "=r"(r[2]), "=r"(r[3]) : "r"(ad));
}
static __device__ __forceinline__ void ldm2(u32& a, u32& b, u32 ad) {
    asm volatile("ldmatrix.sync.aligned.m8n8.x2.shared.b16 {%0,%1}, [%2];"
                 : "=r"(a), "=r"(b) : "r"(ad));
}
static __device__ __forceinline__ void mma_f16(float* c, const u32* a, u32 b0, u32 b1) {
    asm volatile(
        "mma.sync.aligned.m16n8k16.row.col.f32.f16.f16.f32 "
        "{%0,%1,%2,%3}, {%4,%5,%6,%7}, {%8,%9}, {%0,%1,%2,%3};"
        : "+f"(c[0]), "+f"(c[1]), "+f"(c[2]), "+f"(c[3])
        : "r"(a[0]), "r"(a[1]), "r"(a[2]), "r"(a[3]), "r"(b0), "r"(b1));
}
static __device__ __forceinline__ void mma_bf16(float* c, const u32* a, u32 b0, u32 b1) {
    asm volatile(
        "mma.sync.aligned.m16n8k16.row.col.f32.bf16.bf16.f32 "
        "{%0,%1,%2,%3}, {%4,%5,%6,%7}, {%8,%9}, {%0,%1,%2,%3};"
        : "+f"(c[0]), "+f"(c[1]), "+f"(c[2]), "+f"(c[3])
        : "r"(a[0]), "r"(a[1]), "r"(a[2]), "r"(a[3]), "r"(b0), "r"(b1));
}
static __device__ __forceinline__ float sigf(float v) {
    return __fdividef(1.0f, 1.0f + __expf(-v));
}
static __device__ __forceinline__ float tanhf_(float v) {
    return __fdividef(2.0f, 1.0f + __expf(-2.0f * v)) - 1.0f;
}
static __device__ __forceinline__ u32 catb(__nv_bfloat16 a, __nv_bfloat16 b) {
    return (u32)__bfloat16_as_ushort(a) | ((u32)__bfloat16_as_ushort(b) << 16);
}
static __device__ __forceinline__ void split8(const float* v, uint4& h, uint4& l) {
    __nv_bfloat16 bh[8];
    float rr[8];
#pragma unroll
    for (int i = 0; i < 8; i++) {
        bh[i] = __float2bfloat16(v[i]);
        rr[i] = v[i] - __bfloat162float(bh[i]);
    }
    h.x = catb(bh[0], bh[1]); h.y = catb(bh[2], bh[3]);
    h.z = catb(bh[4], bh[5]); h.w = catb(bh[6], bh[7]);
    l.x = catb(__float2bfloat16(rr[0]), __float2bfloat16(rr[1]));
    l.y = catb(__float2bfloat16(rr[2]), __float2bfloat16(rr[3]));
    l.z = catb(__float2bfloat16(rr[4]), __float2bfloat16(rr[5]));
    l.w = catb(__float2bfloat16(rr[6]), __float2bfloat16(rr[7]));
}

// ============================ prepass ======================================
// Block: 256 thr, rows = 32 (covers rec CTAs 2*rg, 2*rg+1), PT timesteps.
__global__ __launch_bounds__(NTH, 1)
void lstm_prepass(const float* __restrict__ x, const float* __restrict__ Wx,
                  const float* __restrict__ bias)
{
    extern __shared__ char smc[];
    const u32 sb = smaddr(smc);
    const int tid = threadIdx.x, w = tid >> 5, lane = tid & 31;
    const int rg = blockIdx.x & 63;
    const int t0 = (int)(blockIdx.x >> 6) * PT;
    const long b0 = (long)rg * 32;

    // Wx (all 512 cols) hi/lo bf16, ldmatrix layout [n][k], 128B rows
    for (int idx = tid; idx < 64 * 512; idx += NTH) {
        int k = idx >> 9, n = idx & 511;
        int col = 128 * (n & 3) + (n >> 2);
        float wv = Wx[k * 512 + col];
        __nv_bfloat16 bh = __float2bfloat16(wv);
        __nv_bfloat16 bl = __float2bfloat16(wv - __bfloat162float(bh));
        u32 off = (u32)(n * 128 + (((k >> 3) ^ (n & 7)) << 4) + (k & 7) * 2);
        *(__nv_bfloat16*)(smc + P_WHI + off) = bh;
        *(__nv_bfloat16*)(smc + P_WLO + off) = bl;
    }

    // fragment decode
    const int amat = lane >> 3, aidx = lane & 7;
    const int arow = ((amat & 1) << 3) + aidx;
    const int aksel = amat >> 1;
    const int a7 = arow & 7;
    const u32 aob0 = sb + P_AHI + (u32)(arow * 128);
    const u32 aob1 = sb + P_AHI + (u32)((arow + 16) * 128);
    const int bl_ = lane & 15, brin = bl_ & 7, bksel = bl_ >> 3;
    u32 bob[8];
#pragma unroll
    for (int nj = 0; nj < 8; nj++)
        bob[nj] = sb + P_WHI + (u32)((64 * w + 8 * nj + brin) * 128);

    // bias per (nj, e)
    const int t4 = lane & 3;
    float b2[8][2];
#pragma unroll
    for (int nj = 0; nj < 8; nj++)
#pragma unroll
        for (int e = 0; e < 2; e++) {
            int n = 64 * w + 8 * nj + 2 * t4 + e;
            b2[nj][e] = bias[128 * (n & 3) + (n >> 2)];
        }

    // A build mapping: thread -> (row 0..31, 8-float chunk)
    const int prow = tid >> 3, pj = tid & 7;
    const float* xbase = x + (b0 + prow) * (long)TFX + 8 * pj;
    const u32 offx = (u32)(prow * 128 + ((pj ^ (prow & 7)) << 4));

    float xv[8];
    {
        float4 q0 = *(const float4*)(xbase + t0 * F_DIM);
        float4 q1 = *(const float4*)(xbase + t0 * F_DIM + 4);
        xv[0]=q0.x; xv[1]=q0.y; xv[2]=q0.z; xv[3]=q0.w;
        xv[4]=q1.x; xv[5]=q1.y; xv[6]=q1.z; xv[7]=q1.w;
    }
    __syncthreads();

    for (int tt = 0; tt < PT; tt++) {
        const int t = t0 + tt;
        uint4 xh, xl;
        split8(xv, xh, xl);
        *(uint4*)(smc + P_AHI + offx) = xh;
        *(uint4*)(smc + P_ALO + offx) = xl;
        __syncthreads();

        if (tt + 1 < PT) {
            float4 q0 = *(const float4*)(xbase + (t + 1) * F_DIM);
            float4 q1 = *(const float4*)(xbase + (t + 1) * F_DIM + 4);
            xv[0]=q0.x; xv[1]=q0.y; xv[2]=q0.z; xv[3]=q0.w;
            xv[4]=q1.x; xv[5]=q1.y; xv[6]=q1.z; xv[7]=q1.w;
        }

        float acc[2][8][4];
#pragma unroll
        for (int mi = 0; mi < 2; mi++)
#pragma unroll
            for (int nj = 0; nj < 8; nj++)
#pragma unroll
                for (int e = 0; e < 4; e++) acc[mi][nj][e] = 0.0f;

#pragma unroll
        for (int ks = 0; ks < 4; ks++) {
            const u32 swA = 16u * (u32)((2 * ks + aksel) ^ a7);
            u32 Ah0[4], Ah1[4], Al0[4], Al1[4];
            ldm4(Ah0, aob0 + swA);
            ldm4(Ah1, aob1 + swA);
            ldm4(Al0, aob0 + swA + 4096);
            ldm4(Al1, aob1 + swA + 4096);
            const u32 swB = 16u * (u32)((2 * ks + bksel) ^ brin);
#pragma unroll
            for (int nj = 0; nj < 8; nj++) {
                u32 bh0, bh1, bl0, bl1;
                ldm2(bh0, bh1, bob[nj] + swB);
                ldm2(bl0, bl1, bob[nj] + swB + 65536);
                mma_bf16(acc[0][nj], Ah0, bh0, bh1);
                mma_bf16(acc[1][nj], Ah1, bh0, bh1);
                mma_bf16(acc[0][nj], Ah0, bl0, bl1);
                mma_bf16(acc[1][nj], Ah1, bl0, bl1);
                mma_bf16(acc[0][nj], Al0, bh0, bh1);
                mma_bf16(acc[1][nj], Al1, bh0, bh1);
            }
        }

        // + bias, store raw quads: g_xz[(2rg+mi)][t][nj][tid][4]
#pragma unroll
        for (int mi = 0; mi < 2; mi++) {
            float* dst = g_xz + ((long)(2 * rg + mi) * T_DIM + t) * 8192 + tid * 4;
#pragma unroll
            for (int nj = 0; nj < 8; nj++) {
                float4 qv;
                qv.x = acc[mi][nj][0] + b2[nj][0];
                qv.y = acc[mi][nj][1] + b2[nj][1];
                qv.z = acc[mi][nj][2] + b2[nj][0];
                qv.w = acc[mi][nj][3] + b2[nj][1];
                *(float4*)(dst + nj * 1024) = qv;
            }
        }
        __syncthreads();
    }
}

// ============================ recurrent ====================================
__global__ __launch_bounds__(NTH, 1)
void lstm_rec(const float* __restrict__ Wh, float* __restrict__ out)
{
    extern __shared__ char smc[];
    const u32 sb = smaddr(smc);
    const int tid = threadIdx.x, w = tid >> 5, lane = tid & 31;
    const int cta = blockIdx.x;
    const long b0 = (long)cta * 16;

    // Wh fp16 [n=512][k=128], ldmatrix layout, 256B rows
    for (int idx = tid; idx < 512 * 128; idx += NTH) {
        int n = idx >> 7, k = idx & 127;
        int col = 128 * (n & 3) + (n >> 2);
        __half hv = __float2half_rn(Wh[k * 512 + col]);
        u32 off = (u32)(n * 256 + (((k >> 3) ^ (n & 7)) << 4) + (k & 7) * 2);
        *(__half*)(smc + R_W + off) = hv;
    }
    // zero both A buffers (h0 = 0)
    for (int i = tid; i < 8192 / 8; i += NTH)
        ((u64*)(smc + R_A))[i] = 0ull;
    __syncthreads();

    // fragment decode
    const int amat = lane >> 3, aidx = lane & 7;
    const int arow = ((amat & 1) << 3) + aidx;
    const int aksel = amat >> 1;
    const int a7 = arow & 7;
    const int bl_ = lane & 15, brin = bl_ & 7, bksel = bl_ >> 3;
    u32 bob[8];
#pragma unroll
    for (int nj = 0; nj < 8; nj++)
        bob[nj] = sb + R_W + (u32)((64 * w + 8 * nj + brin) * 256);

    // hoist B fragments for nj 0..3 (held for all 512 steps)
    u32 Br[8][4][2];
#pragma unroll
    for (int ks = 0; ks < 8; ks++) {
        const u32 swB = 16u * (u32)((2 * ks + bksel) ^ brin);
#pragma unroll
        for (int nj = 0; nj < 4; nj++)
            ldm2(Br[ks][nj][0], Br[ks][nj][1], bob[nj] + swB);
    }

    // epilogue decode
    const int q = lane >> 2, t4 = lane & 3, rs = t4 & 1, hcsel = t4 >> 1;
    const int erow = q + 8 * rs;

    const float* xzp = g_xz + (long)cta * T_DIM * 8192;
    float xz[32];
#pragma unroll
    for (int nj = 0; nj < 8; nj++)
        *(float4*)(xz + 4 * nj) = *(const float4*)(xzp + nj * 1024 + tid * 4);

    float cst[8];
#pragma unroll
    for (int nj = 0; nj < 8; nj++) cst[nj] = 0.0f;

    // out/A-build pass mapping
    const int orow = tid >> 4;
    const int oc8 = (tid & 15) * 8;
    float* outp = out + (b0 + orow) * (long)THX + oc8;
    const u32 abOff = (u32)(orow * 256 + (((oc8 >> 3) ^ (orow & 7)) << 4));

    for (int t = 0; t < T_DIM; t++) {
        __syncthreads();   // A(t) buffer complete; stage free

        const u32 aob = sb + R_A + (u32)((t & 1) * 4096) + (u32)(arow * 256);

        float acc[8][4];
#pragma unroll
        for (int nj = 0; nj < 8; nj++)
#pragma unroll
            for (int e = 0; e < 4; e++) acc[nj][e] = 0.0f;

#pragma unroll
        for (int ks = 0; ks < 8; ks++) {
            u32 A0[4];
            ldm4(A0, aob + 16u * (u32)((2 * ks + aksel) ^ a7));
            const u32 swB = 16u * (u32)((2 * ks + bksel) ^ brin);
            u32 B4[4][2];
#pragma unroll
            for (int nj = 4; nj < 8; nj++)
                ldm2(B4[nj - 4][0], B4[nj - 4][1], bob[nj] + swB);
#pragma unroll
            for (int nj = 0; nj < 4; nj++)
                mma_f16(acc[nj], A0, Br[ks][nj][0], Br[ks][nj][1]);
#pragma unroll
            for (int nj = 4; nj < 8; nj++)
                mma_f16(acc[nj], A0, B4[nj - 4][0], B4[nj - 4][1]);
        }

        // epilogue: z = acc + xz, shfl gate exchange, state update, stage h
#pragma unroll
        for (int nj = 0; nj < 8; nj++) {
            float v0 = acc[nj][0] + xz[4 * nj + 0];
            float v1 = acc[nj][1] + xz[4 * nj + 1];
            float v2 = acc[nj][2] + xz[4 * nj + 2];
            float v3 = acc[nj][3] + xz[4 * nj + 3];
            float p0 = __shfl_xor_sync(0xffffffffu, v0, 1);
            float p1 = __shfl_xor_sync(0xffffffffu, v1, 1);
            float p2 = __shfl_xor_sync(0xffffffffu, v2, 1);
            float p3 = __shfl_xor_sync(0xffffffffu, v3, 1);
            float zi = rs ? p2 : v0;
            float zf = rs ? p3 : v1;
            float zg = rs ? v2 : p0;
            float zo = rs ? v3 : p1;
            float ig = sigf(zi);
            float fg = sigf(zf);
            float gg = tanhf_(zg);
            float og = sigf(zo);
            float cn = fmaf(fg, cst[nj], ig * gg);
            cst[nj] = cn;
            float h = og * tanhf_(cn);
            *(float*)(smc + R_ST + (u32)((erow * 132 + 16 * w + 2 * nj + hcsel) * 4)) = h;
        }

        // prefetch xz(t+1) (after LDSM phase -> never queues ahead of it)
        if (t + 1 < T_DIM) {
            const float* s = xzp + (long)(t + 1) * 8192 + tid * 4;
#pragma unroll
            for (int nj = 0; nj < 8; nj++)
                *(float4*)(xz + 4 * nj) = *(const float4*)(s + nj * 1024);
        }

        __syncthreads();   // stage complete

        // coalesced out write + A(t+1) build from stage
        float hv[8];
        *(float4*)(hv)     = *(const float4*)(smc + R_ST + (u32)((orow * 132 + oc8) * 4));
        *(float4*)(hv + 4) = *(const float4*)(smc + R_ST + (u32)((orow * 132 + oc8 + 4) * 4));
        *(float4*)(outp + (long)t * H_DIM)     = *(const float4*)(hv);
        *(float4*)(outp + (long)t * H_DIM + 4) = *(const float4*)(hv + 4);
        if (t + 1 < T_DIM) {
            uint4 pk;
            pk.x = (u32)__half_as_ushort(__float2half_rn(hv[0])) |
                   ((u32)__half_as_ushort(__float2half_rn(hv[1])) << 16);
            pk.y = (u32)__half_as_ushort(__float2half_rn(hv[2])) |
                   ((u32)__half_as_ushort(__float2half_rn(hv[3])) << 16);
            pk.z = (u32)__half_as_ushort(__float2half_rn(hv[4])) |
                   ((u32)__half_as_ushort(__float2half_rn(hv[5])) << 16);
            pk.w = (u32)__half_as_ushort(__float2half_rn(hv[6])) |
                   ((u32)__half_as_ushort(__float2half_rn(hv[7])) << 16);
            *(uint4*)(smc + R_A + (u32)(((t + 1) & 1) * 4096) + abOff) = pk;
        }
    }
}

extern "C" void kernel_launch(void* const* d_in, const int* in_sizes, int n_in,
                              void* d_out, int out_size) {
    const float* x  = (const float*)d_in[0];   // [B,T,F]
    const float* Wx = (const float*)d_in[1];   // [F,512]
    const float* Wh = (const float*)d_in[2];   // [H,512]
    const float* b  = (const float*)d_in[3];   // [512]
    float* out = (float*)d_out;                // [B,T,H]

    cudaFuncSetAttribute(lstm_prepass, cudaFuncAttributeMaxDynamicSharedMemorySize, SMEM_PRE);
    cudaFuncSetAttribute(lstm_rec, cudaFuncAttributeMaxDynamicSharedMemorySize, SMEM_REC);

    lstm_prepass<<<64 * (T_DIM / PT), NTH, SMEM_PRE>>>(x, Wx, b);
    lstm_rec<<<128, NTH, SMEM_REC>>>(Wh, out);
}

// round 12
// speedup vs baseline: 2.8614x; 1.1983x over previous
#include <cuda_runtime.h>
#include <cuda_fp16.h>
#include <cuda_bf16.h>
#include <cstdint>

// LSTM B=2048,T=512,F=64,H=128.
// Prepass: xz = x@Wx + b (bf16 3-term split, ~fp32 exact), stored as fp16
//   accumulator quads in g_xzh[cta][t][nj][tid] (uint2 = 4 halves).
// Rec: z = xz + h@Wh, single-term fp16 mma.sync, M=16/CTA, N=512, K=128,
//   128 independent CTAs. Gates via tanh.approx (sigmoid = 0.5*tanh(x/2)+0.5).

#define T_DIM 512
#define F_DIM 64
#define H_DIM 128
#define TFX   (T_DIM * F_DIM)
#define THX   (T_DIM * H_DIM)
#define NTH   256
#define PT    64

// rec smem
#define R_W   0
#define R_A   131072            // 2 x 4096 (A fp16 [16][128], double buffer)
#define R_ST  139264            // stage fp32 [16][132]
#define SMEM_REC (139264 + 16*132*4)

// prepass smem
#define P_WHI 0
#define P_WLO 65536
#define P_AHI 131072
#define P_ALO 135168
#define SMEM_PRE 139264

typedef uint32_t u32;
typedef unsigned long long u64;

__device__ uint2 g_xzh[134217728];   // 128 x 512 x 8 x 256 uint2 (1.07 GB)

static __device__ __forceinline__ u32 smaddr(const void* p) {
    u32 a;
    asm("{ .reg .u64 t; cvta.to.shared.u64 t, %1; cvt.u32.u64 %0, t; }" : "=r"(a) : "l"(p));
    return a;
}
static __device__ __forceinline__ void ldm4(u32* r, u32 ad) {
    asm volatile("ldmatrix.sync.aligned.m8n8.x4.shared.b16 {%0,%1,%2,%3}, [%4];"
                 : "=r"(r[0]), "=r"(r[1]), "=r"(r[2]), "=r"(r[3]) : "r"(ad));
}
static __device__ __forceinline__ void ldm2(u32& a, u32& b, u32 ad) {
    asm volatile("ldmatrix.sync.aligned.m8n8.x2.shared.b16 {%0,%1}, [%2];"
                 : "=r"(a), "=r"(b) : "r"(ad));
}
static __device__ __forceinline__ void mma_f16(float* c, const u32* a, u32 b0, u32 b1) {
    asm volatile(
        "mma.sync.aligned.m16n8k16.row.col.f32.f16.f16.f32 "
        "{%0,%1,%2,%3}, {%4,%5,%6,%7}, {%8,%9}, {%0,%1,%2,%3};"
        : "+f"(c[0]), "+f"(c[1]), "+f"(c[2]), "+f"(c[3])
        : "r"(a[0]), "r"(a[1]), "r"(a[2]), "r"(a[3]), "r"(b0), "r"(b1));
}
static __device__ __forceinline__ void mma_bf16(float* c, const u32* a, u32 b0, u32 b1) {
    asm volatile(
        "mma.sync.aligned.m16n8k16.row.col.f32.bf16.bf16.f32 "
        "{%0,%1,%2,%3}, {%4,%5,%6,%7}, {%8,%9}, {%0,%1,%2,%3};"
        : "+f"(c[0]), "+f"(c[1]), "+f"(c[2]), "+f"(c[3])
        : "r"(a[0]), "r"(a[1]), "r"(a[2]), "r"(a[3]), "r"(b0), "r"(b1));
}
static __device__ __forceinline__ float tanh_ap(float x) {
    float r; asm("tanh.approx.f32 %0, %1;" : "=f"(r) : "f"(x)); return r;
}
static __device__ __forceinline__ float sig_ap(float x) {
    return fmaf(0.5f, tanh_ap(0.5f * x), 0.5f);
}
static __device__ __forceinline__ u32 catb(__nv_bfloat16 a, __nv_bfloat16 b) {
    return (u32)__bfloat16_as_ushort(a) | ((u32)__bfloat16_as_ushort(b) << 16);
}
static __device__ __forceinline__ u32 cath(float a, float b) {
    __half2 h2 = __floats2half2_rn(a, b);
    return *(u32*)&h2;
}
static __device__ __forceinline__ void split8(const float* v, uint4& h, uint4& l) {
    __nv_bfloat16 bh[8];
    float rr[8];
#pragma unroll
    for (int i = 0; i < 8; i++) {
        bh[i] = __float2bfloat16(v[i]);
        rr[i] = v[i] - __bfloat162float(bh[i]);
    }
    h.x = catb(bh[0], bh[1]); h.y = catb(bh[2], bh[3]);
    h.z = catb(bh[4], bh[5]); h.w = catb(bh[6], bh[7]);
    l.x = catb(__float2bfloat16(rr[0]), __float2bfloat16(rr[1]));
    l.y = catb(__float2bfloat16(rr[2]), __float2bfloat16(rr[3]));
    l.z = catb(__float2bfloat16(rr[4]), __float2bfloat16(rr[5]));
    l.w = catb(__float2bfloat16(rr[6]), __float2bfloat16(rr[7]));
}

// ============================ prepass ======================================
__global__ __launch_bounds__(NTH, 1)
void lstm_prepass(const float* __restrict__ x, const float* __restrict__ Wx,
                  const float* __restrict__ bias)
{
    extern __shared__ char smc[];
    const u32 sb = smaddr(smc);
    const int tid = threadIdx.x, w = tid >> 5, lane = tid & 31;
    const int rg = blockIdx.x & 63;
    const int t0 = (int)(blockIdx.x >> 6) * PT;
    const long b0 = (long)rg * 32;

    // Wx (all 512 cols) hi/lo bf16, ldmatrix layout [n][k], 128B rows
    for (int idx = tid; idx < 64 * 512; idx += NTH) {
        int k = idx >> 9, n = idx & 511;
        int col = 128 * (n & 3) + (n >> 2);
        float wv = Wx[k * 512 + col];
        __nv_bfloat16 bh = __float2bfloat16(wv);
        __nv_bfloat16 bl = __float2bfloat16(wv - __bfloat162float(bh));
        u32 off = (u32)(n * 128 + (((k >> 3) ^ (n & 7)) << 4) + (k & 7) * 2);
        *(__nv_bfloat16*)(smc + P_WHI + off) = bh;
        *(__nv_bfloat16*)(smc + P_WLO + off) = bl;
    }

    // fragment decode
    const int amat = lane >> 3, aidx = lane & 7;
    const int arow = ((amat & 1) << 3) + aidx;
    const int aksel = amat >> 1;
    const int a7 = arow & 7;
    const u32 aob0 = sb + P_AHI + (u32)(arow * 128);
    const u32 aob1 = sb + P_AHI + (u32)((arow + 16) * 128);
    const int bl_ = lane & 15, brin = bl_ & 7, bksel = bl_ >> 3;
    u32 bob[8];
#pragma unroll
    for (int nj = 0; nj < 8; nj++)
        bob[nj] = sb + P_WHI + (u32)((64 * w + 8 * nj + brin) * 128);

    // bias per (nj, e)
    const int t4 = lane & 3;
    float b2[8][2];
#pragma unroll
    for (int nj = 0; nj < 8; nj++)
#pragma unroll
        for (int e = 0; e < 2; e++) {
            int n = 64 * w + 8 * nj + 2 * t4 + e;
            b2[nj][e] = bias[128 * (n & 3) + (n >> 2)];
        }

    // A build mapping
    const int prow = tid >> 3, pj = tid & 7;
    const float* xbase = x + (b0 + prow) * (long)TFX + 8 * pj;
    const u32 offx = (u32)(prow * 128 + ((pj ^ (prow & 7)) << 4));

    float xv[8];
    {
        float4 q0 = *(const float4*)(xbase + t0 * F_DIM);
        float4 q1 = *(const float4*)(xbase + t0 * F_DIM + 4);
        xv[0]=q0.x; xv[1]=q0.y; xv[2]=q0.z; xv[3]=q0.w;
        xv[4]=q1.x; xv[5]=q1.y; xv[6]=q1.z; xv[7]=q1.w;
    }
    __syncthreads();

    for (int tt = 0; tt < PT; tt++) {
        const int t = t0 + tt;
        uint4 xh, xl;
        split8(xv, xh, xl);
        *(uint4*)(smc + P_AHI + offx) = xh;
        *(uint4*)(smc + P_ALO + offx) = xl;
        __syncthreads();

        if (tt + 1 < PT) {
            float4 q0 = *(const float4*)(xbase + (t + 1) * F_DIM);
            float4 q1 = *(const float4*)(xbase + (t + 1) * F_DIM + 4);
            xv[0]=q0.x; xv[1]=q0.y; xv[2]=q0.z; xv[3]=q0.w;
            xv[4]=q1.x; xv[5]=q1.y; xv[6]=q1.z; xv[7]=q1.w;
        }

        float acc[2][8][4];
#pragma unroll
        for (int mi = 0; mi < 2; mi++)
#pragma unroll
            for (int nj = 0; nj < 8; nj++)
#pragma unroll
                for (int e = 0; e < 4; e++) acc[mi][nj][e] = 0.0f;

#pragma unroll
        for (int ks = 0; ks < 4; ks++) {
            const u32 swA = 16u * (u32)((2 * ks + aksel) ^ a7);
            u32 Ah0[4], Ah1[4], Al0[4], Al1[4];
            ldm4(Ah0, aob0 + swA);
            ldm4(Ah1, aob1 + swA);
            ldm4(Al0, aob0 + swA + 4096);
            ldm4(Al1, aob1 + swA + 4096);
            const u32 swB = 16u * (u32)((2 * ks + bksel) ^ brin);
#pragma unroll
            for (int nj = 0; nj < 8; nj++) {
                u32 bh0, bh1, bl0, bl1;
                ldm2(bh0, bh1, bob[nj] + swB);
                ldm2(bl0, bl1, bob[nj] + swB + 65536);
                mma_bf16(acc[0][nj], Ah0, bh0, bh1);
                mma_bf16(acc[1][nj], Ah1, bh0, bh1);
                mma_bf16(acc[0][nj], Ah0, bl0, bl1);
                mma_bf16(acc[1][nj], Ah1, bl0, bl1);
                mma_bf16(acc[0][nj], Al0, bh0, bh1);
                mma_bf16(acc[1][nj], Al1, bh0, bh1);
            }
        }

        // + bias, pack fp16, store quads: g_xzh[(2rg+mi)][t][nj][tid]
#pragma unroll
        for (int mi = 0; mi < 2; mi++) {
            uint2* dst = g_xzh + ((long)(2 * rg + mi) * T_DIM + t) * 2048 + tid;
#pragma unroll
            for (int nj = 0; nj < 8; nj++) {
                uint2 pk;
                pk.x = cath(acc[mi][nj][0] + b2[nj][0], acc[mi][nj][1] + b2[nj][1]);
                pk.y = cath(acc[mi][nj][2] + b2[nj][0], acc[mi][nj][3] + b2[nj][1]);
                dst[nj * 256] = pk;
            }
        }
        __syncthreads();
    }
}

// ============================ recurrent ====================================
__global__ __launch_bounds__(NTH, 1)
void lstm_rec(const float* __restrict__ Wh, float* __restrict__ out)
{
    extern __shared__ char smc[];
    const u32 sb = smaddr(smc);
    const int tid = threadIdx.x, w = tid >> 5, lane = tid & 31;
    const int cta = blockIdx.x;
    const long b0 = (long)cta * 16;

    // Wh fp16 [n=512][k=128], ldmatrix layout, 256B rows
    for (int idx = tid; idx < 512 * 128; idx += NTH) {
        int n = idx >> 7, k = idx & 127;
        int col = 128 * (n & 3) + (n >> 2);
        __half hv = __float2half_rn(Wh[k * 512 + col]);
        u32 off = (u32)(n * 256 + (((k >> 3) ^ (n & 7)) << 4) + (k & 7) * 2);
        *(__half*)(smc + R_W + off) = hv;
    }
    // zero both A buffers (h0 = 0)
    for (int i = tid; i < 8192 / 8; i += NTH)
        ((u64*)(smc + R_A))[i] = 0ull;
    __syncthreads();

    // fragment decode
    const int amat = lane >> 3, aidx = lane & 7;
    const int arow = ((amat & 1) << 3) + aidx;
    const int aksel = amat >> 1;
    const int a7 = arow & 7;
    const int bl_ = lane & 15, brin = bl_ & 7, bksel = bl_ >> 3;
    u32 bob[8];
#pragma unroll
    for (int nj = 0; nj < 8; nj++)
        bob[nj] = sb + R_W + (u32)((64 * w + 8 * nj + brin) * 256);

    // hoist B fragments for nj 0..3 (held for all 512 steps)
    u32 Br[8][4][2];
#pragma unroll
    for (int ks = 0; ks < 8; ks++) {
        const u32 swB = 16u * (u32)((2 * ks + bksel) ^ brin);
#pragma unroll
        for (int nj = 0; nj < 4; nj++)
            ldm2(Br[ks][nj][0], Br[ks][nj][1], bob[nj] + swB);
    }

    // epilogue decode
    const int q = lane >> 2, t4 = lane & 3, rs = t4 & 1, hcsel = t4 >> 1;
    const int erow = q + 8 * rs;

    const uint2* xzp = g_xzh + (long)cta * T_DIM * 2048;
    uint2 xz[8];
#pragma unroll
    for (int nj = 0; nj < 8; nj++)
        xz[nj] = xzp[nj * 256 + tid];

    float cst[8];
#pragma unroll
    for (int nj = 0; nj < 8; nj++) cst[nj] = 0.0f;

    // out/A-build pass mapping
    const int orow = tid >> 4;
    const int oc8 = (tid & 15) * 8;
    float* outp = out + (b0 + orow) * (long)THX + oc8;
    const u32 abOff = (u32)(orow * 256 + (((oc8 >> 3) ^ (orow & 7)) << 4));

    for (int t = 0; t < T_DIM; t++) {
        __syncthreads();   // A(t) buffer complete; stage free

        const u32 aob = sb + R_A + (u32)((t & 1) * 4096) + (u32)(arow * 256);

        float acc[8][4];
#pragma unroll
        for (int nj = 0; nj < 8; nj++)
#pragma unroll
            for (int e = 0; e < 4; e++) acc[nj][e] = 0.0f;

#pragma unroll
        for (int ks = 0; ks < 8; ks++) {
            u32 A0[4];
            ldm4(A0, aob + 16u * (u32)((2 * ks + aksel) ^ a7));
            const u32 swB = 16u * (u32)((2 * ks + bksel) ^ brin);
            u32 B4[4][2];
#pragma unroll
            for (int nj = 4; nj < 8; nj++)
                ldm2(B4[nj - 4][0], B4[nj - 4][1], bob[nj] + swB);
#pragma unroll
            for (int nj = 0; nj < 4; nj++)
                mma_f16(acc[nj], A0, Br[ks][nj][0], Br[ks][nj][1]);
#pragma unroll
            for (int nj = 4; nj < 8; nj++)
                mma_f16(acc[nj], A0, B4[nj - 4][0], B4[nj - 4][1]);
        }

        // epilogue: z = acc + xz, shfl gate exchange, approx gates, stage h
#pragma unroll
        for (int nj = 0; nj < 8; nj++) {
            float2 xlo = __half22float2(*(__half2*)&xz[nj].x);
            float2 xhi = __half22float2(*(__half2*)&xz[nj].y);
            float v0 = acc[nj][0] + xlo.x;
            float v1 = acc[nj][1] + xlo.y;
            float v2 = acc[nj][2] + xhi.x;
            float v3 = acc[nj][3] + xhi.y;
            float p0 = __shfl_xor_sync(0xffffffffu, v0, 1);
            float p1 = __shfl_xor_sync(0xffffffffu, v1, 1);
            float p2 = __shfl_xor_sync(0xffffffffu, v2, 1);
            float p3 = __shfl_xor_sync(0xffffffffu, v3, 1);
            float zi = rs ? p2 : v0;
            float zf = rs ? p3 : v1;
            float zg = rs ? v2 : p0;
            float zo = rs ? v3 : p1;
            float ig = sig_ap(zi);
            float fg = sig_ap(zf);
            float gg = tanh_ap(zg);
            float og = sig_ap(zo);
            float cn = fmaf(fg, cst[nj], ig * gg);
            cst[nj] = cn;
            float h = og * tanh_ap(cn);
            *(float*)(smc + R_ST + (u32)((erow * 132 + 16 * w + 2 * nj + hcsel) * 4)) = h;
        }

        // prefetch xz(t+1) (after LDSM phase -> never queues ahead of it)
        if (t + 1 < T_DIM) {
            const uint2* s = xzp + (long)(t + 1) * 2048 + tid;
#pragma unroll
            for (int nj = 0; nj < 8; nj++)
                xz[nj] = s[nj * 256];
        }

        __syncthreads();   // stage complete

        // coalesced out write + A(t+1) build from stage
        float hv[8];
        *(float4*)(hv)     = *(const float4*)(smc + R_ST + (u32)((orow * 132 + oc8) * 4));
        *(float4*)(hv + 4) = *(const float4*)(smc + R_ST + (u32)((orow * 132 + oc8 + 4) * 4));
        *(float4*)(outp + (long)t * H_DIM)     = *(const float4*)(hv);
        *(float4*)(outp + (long)t * H_DIM + 4) = *(const float4*)(hv + 4);
        if (t + 1 < T_DIM) {
            uint4 pk;
            pk.x = cath(hv[0], hv[1]);
            pk.y = cath(hv[2], hv[3]);
            pk.z = cath(hv[4], hv[5]);
            pk.w = cath(hv[6], hv[7]);
            *(uint4*)(smc + R_A + (u32)(((t + 1) & 1) * 4096) + abOff) = pk;
        }
    }
}

extern "C" void kernel_launch(void* const* d_in, const int* in_sizes, int n_in,
                              void* d_out, int out_size) {
    const float* x  = (const float*)d_in[0];   // [B,T,F]
    const float* Wx = (const float*)d_in[1];   // [F,512]
    const float* Wh = (const float*)d_in[2];   // [H,512]
    const float* b  = (const float*)d_in[3];   // [512]
    float* out = (float*)d_out;                // [B,T,H]

    cudaFuncSetAttribute(lstm_prepass, cudaFuncAttributeMaxDynamicSharedMemorySize, SMEM_PRE);
    cudaFuncSetAttribute(lstm_rec, cudaFuncAttributeMaxDynamicSharedMemorySize, SMEM_REC);

    lstm_prepass<<<64 * (T_DIM / PT), NTH, SMEM_PRE>>>(x, Wx, b);
    lstm_rec<<<128, NTH, SMEM_REC>>>(Wh, out);
}

// round 13
// speedup vs baseline: 3.3969x; 1.1871x over previous
#include <cuda_runtime.h>
#include <cuda_fp16.h>
#include <cuda_bf16.h>
#include <cstdint>

// LSTM B=2048,T=512,F=64,H=128.
// Prepass: xz = x@Wx + b as a batched GEMM, single-term fp16 mma.
//   M=128 (16 batch rows x 8 timesteps; tile mi == timestep), N=512, K=64.
//   Stored as fp16 quads g_xzh[cta][t][nj][tid] in the rec fragment layout.
// Rec: z = xz + h@Wh, single-term fp16 mma, M=16/CTA, N=512, K=128,
//   128 independent CTAs. Gates via tanh.approx.

#define T_DIM 512
#define F_DIM 64
#define H_DIM 128
#define TFX   (T_DIM * F_DIM)
#define THX   (T_DIM * H_DIM)
#define NTH   256

// rec smem
#define R_W   0
#define R_A   131072            // 2 x 4096 (A fp16 [16][128], double buffer)
#define R_ST  139264            // stage fp32 [16][132]
#define SMEM_REC (139264 + 16*132*4)

// prepass smem
#define P_W   0                 // W fp16 [512][64] ldmatrix layout, 64KB
#define P_A   65536             // A fp16 [128][64], double buffer 2x16KB
#define SMEM_PRE 98304

typedef uint32_t u32;
typedef unsigned long long u64;

__device__ uint2 g_xzh[134217728];   // 128 x 512 x 8 x 256 uint2 (1.07 GB)

static __device__ __forceinline__ u32 smaddr(const void* p) {
    u32 a;
    asm("{ .reg .u64 t; cvta.to.shared.u64 t, %1; cvt.u32.u64 %0, t; }" : "=r"(a) : "l"(p));
    return a;
}
static __device__ __forceinline__ void ldm4(u32* r, u32 ad) {
    asm volatile("ldmatrix.sync.aligned.m8n8.x4.shared.b16 {%0,%1,%2,%3}, [%4];"
                 : "=r"(r[0]), "=r"(r[1]), "=r"(r[2]), "=r"(r[3]) : "r"(ad));
}
static __device__ __forceinline__ void ldm2(u32& a, u32& b, u32 ad) {
    asm volatile("ldmatrix.sync.aligned.m8n8.x2.shared.b16 {%0,%1}, [%2];"
                 : "=r"(a), "=r"(b) : "r"(ad));
}
static __device__ __forceinline__ void mma_f16(float* c, const u32* a, u32 b0, u32 b1) {
    asm volatile(
        "mma.sync.aligned.m16n8k16.row.col.f32.f16.f16.f32 "
        "{%0,%1,%2,%3}, {%4,%5,%6,%7}, {%8,%9}, {%0,%1,%2,%3};"
        : "+f"(c[0]), "+f"(c[1]), "+f"(c[2]), "+f"(c[3])
        : "r"(a[0]), "r"(a[1]), "r"(a[2]), "r"(a[3]), "r"(b0), "r"(b1));
}
static __device__ __forceinline__ float tanh_ap(float x) {
    float r; asm("tanh.approx.f32 %0, %1;" : "=f"(r) : "f"(x)); return r;
}
static __device__ __forceinline__ float sig_ap(float x) {
    return fmaf(0.5f, tanh_ap(0.5f * x), 0.5f);
}
static __device__ __forceinline__ u32 cath(float a, float b) {
    __half2 h2 = __floats2half2_rn(a, b);
    return *(u32*)&h2;
}

// ============================ prepass ======================================
// 512 blocks: blockIdx -> (cta = bid>>2, t-quarter = bid&3 -> 128 timesteps).
// 16 iterations x 8 timesteps. A tile [row = 16*tt + b][k], double-buffered.
__global__ __launch_bounds__(NTH)
void lstm_prepass(const float* __restrict__ x, const float* __restrict__ Wx,
                  const float* __restrict__ bias)
{
    extern __shared__ char smc[];
    const u32 sb = smaddr(smc);
    const int tid = threadIdx.x, w = tid >> 5, lane = tid & 31;
    const int cta = blockIdx.x >> 2;
    const int t0 = (blockIdx.x & 3) * 128;
    const long b0 = (long)cta * 16;

    // W fp16, ldmatrix layout [n=512][k=64], 128B rows
    for (int idx = tid; idx < 512 * 64; idx += NTH) {
        int n = idx >> 6, k = idx & 63;
        int col = 128 * (n & 3) + (n >> 2);
        __half hv = __float2half_rn(Wx[k * 512 + col]);
        u32 off = (u32)(n * 128 + (((k >> 3) ^ (n & 7)) << 4) + (k & 7) * 2);
        *(__half*)(smc + P_W + off) = hv;
    }
    __syncthreads();

    // fragment decode
    const int amat = lane >> 3, aidx = lane & 7;
    const int arow = ((amat & 1) << 3) + aidx;
    const int aksel = amat >> 1;
    const int a7 = arow & 7;
    const int bl_ = lane & 15, brin = bl_ & 7, bksel = bl_ >> 3;

    // hoist ALL B fragments (8 nj x 4 ks), reused for 128 timesteps
    u32 Br[4][8][2];
#pragma unroll
    for (int ks = 0; ks < 4; ks++) {
        const u32 swB = 16u * (u32)((2 * ks + bksel) ^ brin);
#pragma unroll
        for (int nj = 0; nj < 8; nj++)
            ldm2(Br[ks][nj][0], Br[ks][nj][1],
                 sb + P_W + (u32)((64 * w + 8 * nj + brin) * 128) + swB);
    }

    // bias per (nj, e)
    const int t4 = lane & 3;
    float b2[8][2];
#pragma unroll
    for (int nj = 0; nj < 8; nj++)
#pragma unroll
        for (int e = 0; e < 2; e++) {
            int n = 64 * w + 8 * nj + 2 * t4 + e;
            b2[nj][e] = bias[128 * (n & 3) + (n >> 2)];
        }

    // A build mapping: thread -> (row = 16*tt + b, half-row part)
    const int brow = tid >> 1, part = tid & 1;
    const int tt = brow >> 4, bb = brow & 15;
    const float* xbase = x + (b0 + bb) * (long)TFX + (t0 + tt) * F_DIM + 32 * part;
    u32 aoff[4];
#pragma unroll
    for (int j = 0; j < 4; j++)
        aoff[j] = (u32)(brow * 128 + (((4 * part + j) ^ (brow & 7)) << 4));

    // build A for iteration 'it' into buffer 'buf'
    auto build = [&](int it, int buf) {
        const float* s = xbase + it * 8 * F_DIM;
        float4 q[8];
#pragma unroll
        for (int j = 0; j < 8; j++) q[j] = *(const float4*)(s + 4 * j);
        const u32 base = sb + P_A + (u32)(buf * 16384);
#pragma unroll
        for (int j = 0; j < 4; j++) {
            uint4 pk;
            pk.x = cath(q[2 * j].x, q[2 * j].y);
            pk.y = cath(q[2 * j].z, q[2 * j].w);
            pk.z = cath(q[2 * j + 1].x, q[2 * j + 1].y);
            pk.w = cath(q[2 * j + 1].z, q[2 * j + 1].w);
            *(uint4*)(smc + (base - sb) + aoff[j]) = pk;
        }
    };

    build(0, 0);
    __syncthreads();

    for (int it = 0; it < 16; it++) {
        if (it + 1 < 16) build(it + 1, (it + 1) & 1);   // other buffer: no sync needed

        const u32 ab = sb + P_A + (u32)((it & 1) * 16384);
#pragma unroll
        for (int mi = 0; mi < 8; mi++) {
            float acc[8][4];
#pragma unroll
            for (int nj = 0; nj < 8; nj++)
#pragma unroll
                for (int e = 0; e < 4; e++) acc[nj][e] = 0.0f;

#pragma unroll
            for (int ks = 0; ks < 4; ks++) {
                u32 A0[4];
                ldm4(A0, ab + (u32)((16 * mi + arow) * 128)
                         + 16u * (u32)((2 * ks + aksel) ^ a7));
#pragma unroll
                for (int nj = 0; nj < 8; nj++)
                    mma_f16(acc[nj], A0, Br[ks][nj][0], Br[ks][nj][1]);
            }

            // + bias, pack fp16, store quads
            const int t = t0 + 8 * it + mi;
            uint2* dst = g_xzh + ((long)cta * T_DIM + t) * 2048 + tid;
#pragma unroll
            for (int nj = 0; nj < 8; nj++) {
                uint2 pk;
                pk.x = cath(acc[nj][0] + b2[nj][0], acc[nj][1] + b2[nj][1]);
                pk.y = cath(acc[nj][2] + b2[nj][0], acc[nj][3] + b2[nj][1]);
                dst[nj * 256] = pk;
            }
        }
        __syncthreads();   // MMA reads of buf(it&1) done; build(it+2) may overwrite
    }
}

// ============================ recurrent ====================================
__global__ __launch_bounds__(NTH)
void lstm_rec(const float* __restrict__ Wh, float* __restrict__ out)
{
    extern __shared__ char smc[];
    const u32 sb = smaddr(smc);
    const int tid = threadIdx.x, w = tid >> 5, lane = tid & 31;
    const int cta = blockIdx.x;
    const long b0 = (long)cta * 16;

    // Wh fp16 [n=512][k=128], ldmatrix layout, 256B rows
    for (int idx = tid; idx < 512 * 128; idx += NTH) {
        int n = idx >> 7, k = idx & 127;
        int col = 128 * (n & 3) + (n >> 2);
        __half hv = __float2half_rn(Wh[k * 512 + col]);
        u32 off = (u32)(n * 256 + (((k >> 3) ^ (n & 7)) << 4) + (k & 7) * 2);
        *(__half*)(smc + R_W + off) = hv;
    }
    // zero both A buffers (h0 = 0)
    for (int i = tid; i < 8192 / 8; i += NTH)
        ((u64*)(smc + R_A))[i] = 0ull;
    __syncthreads();

    // fragment decode
    const int amat = lane >> 3, aidx = lane & 7;
    const int arow = ((amat & 1) << 3) + aidx;
    const int aksel = amat >> 1;
    const int a7 = arow & 7;
    const int bl_ = lane & 15, brin = bl_ & 7, bksel = bl_ >> 3;
    u32 bob[8];
#pragma unroll
    for (int nj = 0; nj < 8; nj++)
        bob[nj] = sb + R_W + (u32)((64 * w + 8 * nj + brin) * 256);

    // hoist B fragments for nj 0..3 (held for all 512 steps)
    u32 Br[8][4][2];
#pragma unroll
    for (int ks = 0; ks < 8; ks++) {
        const u32 swB = 16u * (u32)((2 * ks + bksel) ^ brin);
#pragma unroll
        for (int nj = 0; nj < 4; nj++)
            ldm2(Br[ks][nj][0], Br[ks][nj][1], bob[nj] + swB);
    }

    // epilogue decode
    const int q = lane >> 2, t4 = lane & 3, rs = t4 & 1, hcsel = t4 >> 1;
    const int erow = q + 8 * rs;

    const uint2* xzp = g_xzh + (long)cta * T_DIM * 2048;
    uint2 xz[8];
#pragma unroll
    for (int nj = 0; nj < 8; nj++)
        xz[nj] = xzp[nj * 256 + tid];

    float cst[8];
#pragma unroll
    for (int nj = 0; nj < 8; nj++) cst[nj] = 0.0f;

    // out/A-build pass mapping
    const int orow = tid >> 4;
    const int oc8 = (tid & 15) * 8;
    float* outp = out + (b0 + orow) * (long)THX + oc8;
    const u32 abOff = (u32)(orow * 256 + (((oc8 >> 3) ^ (orow & 7)) << 4));

    for (int t = 0; t < T_DIM; t++) {
        __syncthreads();   // A(t) buffer complete; stage free

        const u32 aob = sb + R_A + (u32)((t & 1) * 4096) + (u32)(arow * 256);

        float acc[8][4];
#pragma unroll
        for (int nj = 0; nj < 8; nj++)
#pragma unroll
            for (int e = 0; e < 4; e++) acc[nj][e] = 0.0f;

#pragma unroll
        for (int ks = 0; ks < 8; ks++) {
            u32 A0[4];
            ldm4(A0, aob + 16u * (u32)((2 * ks + aksel) ^ a7));
            const u32 swB = 16u * (u32)((2 * ks + bksel) ^ brin);
            u32 B4[4][2];
#pragma unroll
            for (int nj = 4; nj < 8; nj++)
                ldm2(B4[nj - 4][0], B4[nj - 4][1], bob[nj] + swB);
#pragma unroll
            for (int nj = 0; nj < 4; nj++)
                mma_f16(acc[nj], A0, Br[ks][nj][0], Br[ks][nj][1]);
#pragma unroll
            for (int nj = 4; nj < 8; nj++)
                mma_f16(acc[nj], A0, B4[nj - 4][0], B4[nj - 4][1]);
        }

        // epilogue: z = acc + xz, shfl gate exchange, approx gates, stage h
#pragma unroll
        for (int nj = 0; nj < 8; nj++) {
            float2 xlo = __half22float2(*(__half2*)&xz[nj].x);
            float2 xhi = __half22float2(*(__half2*)&xz[nj].y);
            float v0 = acc[nj][0] + xlo.x;
            float v1 = acc[nj][1] + xlo.y;
            float v2 = acc[nj][2] + xhi.x;
            float v3 = acc[nj][3] + xhi.y;
            float p0 = __shfl_xor_sync(0xffffffffu, v0, 1);
            float p1 = __shfl_xor_sync(0xffffffffu, v1, 1);
            float p2 = __shfl_xor_sync(0xffffffffu, v2, 1);
            float p3 = __shfl_xor_sync(0xffffffffu, v3, 1);
            float zi = rs ? p2 : v0;
            float zf = rs ? p3 : v1;
            float zg = rs ? v2 : p0;
            float zo = rs ? v3 : p1;
            float ig = sig_ap(zi);
            float fg = sig_ap(zf);
            float gg = tanh_ap(zg);
            float og = sig_ap(zo);
            float cn = fmaf(fg, cst[nj], ig * gg);
            cst[nj] = cn;
            float h = og * tanh_ap(cn);
            *(float*)(smc + R_ST + (u32)((erow * 132 + 16 * w + 2 * nj + hcsel) * 4)) = h;
        }

        // prefetch xz(t+1) (after LDSM phase -> never queues ahead of it)
        if (t + 1 < T_DIM) {
            const uint2* s = xzp + (long)(t + 1) * 2048 + tid;
#pragma unroll
            for (int nj = 0; nj < 8; nj++)
                xz[nj] = s[nj * 256];
        }

        __syncthreads();   // stage complete

        // coalesced out write + A(t+1) build from stage
        float hv[8];
        *(float4*)(hv)     = *(const float4*)(smc + R_ST + (u32)((orow * 132 + oc8) * 4));
        *(float4*)(hv + 4) = *(const float4*)(smc + R_ST + (u32)((orow * 132 + oc8 + 4) * 4));
        *(float4*)(outp + (long)t * H_DIM)     = *(const float4*)(hv);
        *(float4*)(outp + (long)t * H_DIM + 4) = *(const float4*)(hv + 4);
        if (t + 1 < T_DIM) {
            uint4 pk;
            pk.x = cath(hv[0], hv[1]);
            pk.y = cath(hv[2], hv[3]);
            pk.z = cath(hv[4], hv[5]);
            pk.w = cath(hv[6], hv[7]);
            *(uint4*)(smc + R_A + (u32)(((t + 1) & 1) * 4096) + abOff) = pk;
        }
    }
}

extern "C" void kernel_launch(void* const* d_in, const int* in_sizes, int n_in,
                              void* d_out, int out_size) {
    const float* x  = (const float*)d_in[0];   // [B,T,F]
    const float* Wx = (const float*)d_in[1];   // [F,512]
    const float* Wh = (const float*)d_in[2];   // [H,512]
    const float* b  = (const float*)d_in[3];   // [512]
    float* out = (float*)d_out;                // [B,T,H]

    cudaFuncSetAttribute(lstm_prepass, cudaFuncAttributeMaxDynamicSharedMemorySize, SMEM_PRE);
    cudaFuncSetAttribute(lstm_rec, cudaFuncAttributeMaxDynamicSharedMemorySize, SMEM_REC);

    lstm_prepass<<<512, NTH, SMEM_PRE>>>(x, Wx, b);
    lstm_rec<<<128, NTH, SMEM_REC>>>(Wh, out);
}